// round 7
// baseline (speedup 1.0000x reference)
#include <cuda_runtime.h>
#include <cuda_bf16.h>

// Scalar reduction: mean over all elements of
//   term = (a<0 && b<0) ? (b - 2a)^2 : b^2
// where a = target (d_in[1]), b = source (d_in[0]).
// Derivation: fdback - a = (a<0&&b<0) ? (b-a)-a = b-2a : (a-b)-a = -b.
//
// Single-kernel, self-resetting (graph-replay-safe) reduction.
// Hot loop accumulates in FLOAT (2 independent accumulators, one per ILP
// stream) to keep the slow Blackwell FP64 pipe out of the streaming loop;
// doubles are used only from the per-thread epilogue onward.

__device__ double       g_fdloss_sum;    // zero-initialized at module load
__device__ unsigned int g_fdloss_tick;   // zero-initialized; self-wrapping

__global__ __launch_bounds__(256) void fdloss_kernel(
    const float4* __restrict__ src,   // b
    const float4* __restrict__ tgt,   // a
    int n4,
    float* __restrict__ out,
    double inv_n)
{
    const int stride = gridDim.x * blockDim.x;
    int i = blockIdx.x * blockDim.x + threadIdx.x;

    float accf0 = 0.f;
    float accf1 = 0.f;

    // 2-way ILP over float4 pairs; default cache policy (LDG.E.128)
    for (; i + stride < n4; i += 2 * stride) {
        float4 b0 = src[i];
        float4 a0 = tgt[i];
        float4 b1 = src[i + stride];
        float4 a1 = tgt[i + stride];

        {
            float t, s;
            t = (a0.x < 0.f && b0.x < 0.f) ? (b0.x - 2.f * a0.x) : b0.x;
            s = t * t;
            t = (a0.y < 0.f && b0.y < 0.f) ? (b0.y - 2.f * a0.y) : b0.y;
            s += t * t;
            t = (a0.z < 0.f && b0.z < 0.f) ? (b0.z - 2.f * a0.z) : b0.z;
            s += t * t;
            t = (a0.w < 0.f && b0.w < 0.f) ? (b0.w - 2.f * a0.w) : b0.w;
            s += t * t;
            accf0 += s;
        }
        {
            float t, s;
            t = (a1.x < 0.f && b1.x < 0.f) ? (b1.x - 2.f * a1.x) : b1.x;
            s = t * t;
            t = (a1.y < 0.f && b1.y < 0.f) ? (b1.y - 2.f * a1.y) : b1.y;
            s += t * t;
            t = (a1.z < 0.f && b1.z < 0.f) ? (b1.z - 2.f * a1.z) : b1.z;
            s += t * t;
            t = (a1.w < 0.f && b1.w < 0.f) ? (b1.w - 2.f * a1.w) : b1.w;
            s += t * t;
            accf1 += s;
        }
    }
    // tail (at most one float4 per thread)
    if (i < n4) {
        float4 b0 = src[i];
        float4 a0 = tgt[i];
        float t, s;
        t = (a0.x < 0.f && b0.x < 0.f) ? (b0.x - 2.f * a0.x) : b0.x;
        s = t * t;
        t = (a0.y < 0.f && b0.y < 0.f) ? (b0.y - 2.f * a0.y) : b0.y;
        s += t * t;
        t = (a0.z < 0.f && b0.z < 0.f) ? (b0.z - 2.f * a0.z) : b0.z;
        s += t * t;
        t = (a0.w < 0.f && b0.w < 0.f) ? (b0.w - 2.f * a0.w) : b0.w;
        s += t * t;
        accf0 += s;
    }

    // doubles only from here on (epilogue — off the memory-paced path)
    double acc = (double)accf0 + (double)accf1;

    // warp reduce (double)
    #pragma unroll
    for (int off = 16; off > 0; off >>= 1)
        acc += __shfl_down_sync(0xFFFFFFFFu, acc, off);

    __shared__ double warp_sums[8];  // 256 threads = 8 warps
    const int lane = threadIdx.x & 31;
    const int wid  = threadIdx.x >> 5;
    if (lane == 0) warp_sums[wid] = acc;
    __syncthreads();

    __shared__ bool is_last;
    if (threadIdx.x == 0) {
        double v = warp_sums[0];
        #pragma unroll
        for (int w = 1; w < 8; w++) v += warp_sums[w];
        atomicAdd(&g_fdloss_sum, v);
        __threadfence();
        // atomicInc wraps: when old == gridDim.x-1, new value = 0 (self-reset)
        unsigned int ticket = atomicInc(&g_fdloss_tick, gridDim.x - 1u);
        is_last = (ticket == gridDim.x - 1u);
    }
    __syncthreads();

    if (is_last && threadIdx.x == 0) {
        __threadfence();  // see all blocks' atomicAdds
        double s = g_fdloss_sum;
        out[0] = (float)(s * inv_n);
        g_fdloss_sum = 0.0;  // restore initial state for next graph replay
    }
}

extern "C" void kernel_launch(void* const* d_in, const int* in_sizes, int n_in,
                              void* d_out, int out_size) {
    const float* src = (const float*)d_in[0];  // source -> b
    const float* tgt = (const float*)d_in[1];  // target -> a
    float* out = (float*)d_out;

    const long long n = (long long)in_sizes[0];
    const int n4 = (int)(n / 4);   // n = 51,380,224 -> n4 = 12,845,056 (fits int32)

    const int threads = 256;
    long long max_blocks = ((long long)n4 + threads - 1) / threads;
    int blocks = 148 * 8;
    if ((long long)blocks > max_blocks) blocks = (int)max_blocks;
    if (blocks < 1) blocks = 1;

    fdloss_kernel<<<blocks, threads>>>(
        (const float4*)src, (const float4*)tgt, n4, out, 1.0 / (double)n);
}

// round 8
// speedup vs baseline: 1.0250x; 1.0250x over previous
#include <cuda_runtime.h>
#include <cuda_bf16.h>

// Scalar reduction: mean over all elements of
//   term = (a<0 && b<0) ? (b - 2a)^2 : b^2
// where a = target (d_in[1]), b = source (d_in[0]).
// Derivation: fdback - a = (a<0&&b<0) ? (b-a)-a = b-2a : (a-b)-a = -b.
//
// Single-kernel, self-resetting (graph-replay-safe) reduction with DYNAMIC
// chunk scheduling: persistent blocks pull contiguous 1024-float4 chunks off
// a global atomic ticket (prefetched one chunk ahead so the ATOMG latency
// hides under the current chunk's loads). This removes the static-partition
// tail caused by between-SM speed variance. Float accumulation in the hot
// loop; doubles only in the epilogue reduce.

__device__ double       g_fdloss_sum;    // zero-init at load; last block resets
__device__ unsigned int g_fdloss_tick;   // wrapping ticket; self-resets
__device__ unsigned int g_fdloss_work;   // chunk counter; last block resets

#define CHUNK_F4 1024   // float4 elements per chunk (per array) = 16 KB/array

__global__ __launch_bounds__(256) void fdloss_kernel(
    const float4* __restrict__ src,   // b
    const float4* __restrict__ tgt,   // a
    int n4,
    int nchunk_total,                 // ceil-div chunks incl. partial tail chunk
    int nchunk_full,                  // number of full chunks
    float* __restrict__ out,
    double inv_n)
{
    const int t = threadIdx.x;

    float accf0 = 0.f;
    float accf1 = 0.f;

    __shared__ int s_chunk;
    if (t == 0) s_chunk = (int)atomicAdd(&g_fdloss_work, 1u);
    __syncthreads();
    int chunk = s_chunk;

    while (chunk < nchunk_total) {
        __syncthreads();  // everyone has captured s_chunk into `chunk`
        if (t == 0) s_chunk = (int)atomicAdd(&g_fdloss_work, 1u);  // prefetch

        const int base = chunk * CHUNK_F4;

        if (chunk < nchunk_full) {
            // full chunk: 4 float4 per thread as 2 ILP pairs, contiguous spans
            const int i0 = base + t;
            #pragma unroll
            for (int k = 0; k < 2; k++) {
                const int ia = i0 + k * 512;
                float4 b0 = src[ia];
                float4 a0 = tgt[ia];
                float4 b1 = src[ia + 256];
                float4 a1 = tgt[ia + 256];
                {
                    float u, s;
                    u = (a0.x < 0.f && b0.x < 0.f) ? (b0.x - 2.f * a0.x) : b0.x;
                    s = u * u;
                    u = (a0.y < 0.f && b0.y < 0.f) ? (b0.y - 2.f * a0.y) : b0.y;
                    s += u * u;
                    u = (a0.z < 0.f && b0.z < 0.f) ? (b0.z - 2.f * a0.z) : b0.z;
                    s += u * u;
                    u = (a0.w < 0.f && b0.w < 0.f) ? (b0.w - 2.f * a0.w) : b0.w;
                    s += u * u;
                    accf0 += s;
                }
                {
                    float u, s;
                    u = (a1.x < 0.f && b1.x < 0.f) ? (b1.x - 2.f * a1.x) : b1.x;
                    s = u * u;
                    u = (a1.y < 0.f && b1.y < 0.f) ? (b1.y - 2.f * a1.y) : b1.y;
                    s += u * u;
                    u = (a1.z < 0.f && b1.z < 0.f) ? (b1.z - 2.f * a1.z) : b1.z;
                    s += u * u;
                    u = (a1.w < 0.f && b1.w < 0.f) ? (b1.w - 2.f * a1.w) : b1.w;
                    s += u * u;
                    accf1 += s;
                }
            }
        } else {
            // tail chunk (only if n4 % CHUNK_F4 != 0): bounds-checked
            for (int i = base + t; i < n4; i += 256) {
                float4 b0 = src[i];
                float4 a0 = tgt[i];
                float u, s;
                u = (a0.x < 0.f && b0.x < 0.f) ? (b0.x - 2.f * a0.x) : b0.x;
                s = u * u;
                u = (a0.y < 0.f && b0.y < 0.f) ? (b0.y - 2.f * a0.y) : b0.y;
                s += u * u;
                u = (a0.z < 0.f && b0.z < 0.f) ? (b0.z - 2.f * a0.z) : b0.z;
                s += u * u;
                u = (a0.w < 0.f && b0.w < 0.f) ? (b0.w - 2.f * a0.w) : b0.w;
                s += u * u;
                accf0 += s;
            }
        }

        __syncthreads();  // prefetched s_chunk is written and visible
        chunk = s_chunk;
    }

    // doubles only from here on (off the memory-paced path)
    double acc = (double)accf0 + (double)accf1;

    // warp reduce (double)
    #pragma unroll
    for (int off = 16; off > 0; off >>= 1)
        acc += __shfl_down_sync(0xFFFFFFFFu, acc, off);

    __shared__ double warp_sums[8];  // 256 threads = 8 warps
    const int lane = t & 31;
    const int wid  = t >> 5;
    if (lane == 0) warp_sums[wid] = acc;
    __syncthreads();

    __shared__ bool is_last;
    if (t == 0) {
        double v = warp_sums[0];
        #pragma unroll
        for (int w = 1; w < 8; w++) v += warp_sums[w];
        atomicAdd(&g_fdloss_sum, v);
        __threadfence();
        // wrapping ticket: when old == gridDim.x-1, counter resets to 0
        unsigned int ticket = atomicInc(&g_fdloss_tick, gridDim.x - 1u);
        is_last = (ticket == gridDim.x - 1u);
    }
    __syncthreads();

    if (is_last && t == 0) {
        __threadfence();  // see all blocks' atomicAdds
        double s = g_fdloss_sum;
        out[0] = (float)(s * inv_n);
        g_fdloss_sum = 0.0;                  // restore state for next replay
        atomicExch(&g_fdloss_work, 0u);      // restore work counter
    }
}

extern "C" void kernel_launch(void* const* d_in, const int* in_sizes, int n_in,
                              void* d_out, int out_size) {
    const float* src = (const float*)d_in[0];  // source -> b
    const float* tgt = (const float*)d_in[1];  // target -> a
    float* out = (float*)d_out;

    const long long n = (long long)in_sizes[0];
    const int n4 = (int)(n / 4);   // n = 51,380,224 -> n4 = 12,845,056

    const int nchunk_full  = n4 / CHUNK_F4;                 // 12544 (exact)
    const int rem          = n4 - nchunk_full * CHUNK_F4;   // 0 for this shape
    const int nchunk_total = nchunk_full + (rem ? 1 : 0);

    const int threads = 256;
    int blocks = 148 * 8;
    if (blocks > nchunk_total) blocks = nchunk_total;
    if (blocks < 1) blocks = 1;

    fdloss_kernel<<<blocks, threads>>>(
        (const float4*)src, (const float4*)tgt, n4,
        nchunk_total, nchunk_full, out, 1.0 / (double)n);
}

// round 9
// speedup vs baseline: 1.0271x; 1.0020x over previous
#include <cuda_runtime.h>
#include <cuda_bf16.h>

// Scalar reduction: mean over all elements of
//   term = (a<0 && b<0) ? (b - 2a)^2 : b^2
// where a = target (d_in[1]), b = source (d_in[0]).
// Derivation: fdback - a = (a<0&&b<0) ? (b-a)-a = b-2a : (a-b)-a = -b.
//
// Single-kernel, self-resetting (graph-replay-safe) reduction with dynamic
// chunk scheduling. Hot path front-batches ALL 8 LDG.128 of a chunk slice
// (4 src + 4 tgt) before any compute, maximizing per-warp MLP so the SM
// keeps >40KB of reads in flight (vs ~24KB needed to cover DRAM latency).

__device__ double       g_fdloss_sum;    // zero-init at load; last block resets
__device__ unsigned int g_fdloss_tick;   // wrapping ticket; self-resets
__device__ unsigned int g_fdloss_work;   // chunk counter; last block resets

#define CHUNK_F4 1024   // float4 per chunk per array = 16 KB/array

__global__ __launch_bounds__(256) void fdloss_kernel(
    const float4* __restrict__ src,   // b
    const float4* __restrict__ tgt,   // a
    int n4,
    int nchunk_total,
    int nchunk_full,
    float* __restrict__ out,
    double inv_n)
{
    const int t = threadIdx.x;

    float acc0 = 0.f, acc1 = 0.f, acc2 = 0.f, acc3 = 0.f;

    __shared__ int s_chunk;
    if (t == 0) s_chunk = (int)atomicAdd(&g_fdloss_work, 1u);
    __syncthreads();
    int chunk = s_chunk;

    while (chunk < nchunk_total) {
        __syncthreads();  // all threads captured s_chunk
        if (t == 0) s_chunk = (int)atomicAdd(&g_fdloss_work, 1u);  // prefetch

        const int base = chunk * CHUNK_F4;

        if (chunk < nchunk_full) {
            const int i0 = base + t;
            // ---- front-batch all 8 loads (MLP_p1 = 8) ----
            float4 B[4], A[4];
            #pragma unroll
            for (int k = 0; k < 4; k++) {
                B[k] = src[i0 + k * 256];
                A[k] = tgt[i0 + k * 256];
            }
            // ---- compute, 4 independent accumulators ----
            {
                float u, s;
                u = (A[0].x < 0.f && B[0].x < 0.f) ? (B[0].x - 2.f * A[0].x) : B[0].x;
                s = u * u;
                u = (A[0].y < 0.f && B[0].y < 0.f) ? (B[0].y - 2.f * A[0].y) : B[0].y;
                s += u * u;
                u = (A[0].z < 0.f && B[0].z < 0.f) ? (B[0].z - 2.f * A[0].z) : B[0].z;
                s += u * u;
                u = (A[0].w < 0.f && B[0].w < 0.f) ? (B[0].w - 2.f * A[0].w) : B[0].w;
                s += u * u;
                acc0 += s;
            }
            {
                float u, s;
                u = (A[1].x < 0.f && B[1].x < 0.f) ? (B[1].x - 2.f * A[1].x) : B[1].x;
                s = u * u;
                u = (A[1].y < 0.f && B[1].y < 0.f) ? (B[1].y - 2.f * A[1].y) : B[1].y;
                s += u * u;
                u = (A[1].z < 0.f && B[1].z < 0.f) ? (B[1].z - 2.f * A[1].z) : B[1].z;
                s += u * u;
                u = (A[1].w < 0.f && B[1].w < 0.f) ? (B[1].w - 2.f * A[1].w) : B[1].w;
                s += u * u;
                acc1 += s;
            }
            {
                float u, s;
                u = (A[2].x < 0.f && B[2].x < 0.f) ? (B[2].x - 2.f * A[2].x) : B[2].x;
                s = u * u;
                u = (A[2].y < 0.f && B[2].y < 0.f) ? (B[2].y - 2.f * A[2].y) : B[2].y;
                s += u * u;
                u = (A[2].z < 0.f && B[2].z < 0.f) ? (B[2].z - 2.f * A[2].z) : B[2].z;
                s += u * u;
                u = (A[2].w < 0.f && B[2].w < 0.f) ? (B[2].w - 2.f * A[2].w) : B[2].w;
                s += u * u;
                acc2 += s;
            }
            {
                float u, s;
                u = (A[3].x < 0.f && B[3].x < 0.f) ? (B[3].x - 2.f * A[3].x) : B[3].x;
                s = u * u;
                u = (A[3].y < 0.f && B[3].y < 0.f) ? (B[3].y - 2.f * A[3].y) : B[3].y;
                s += u * u;
                u = (A[3].z < 0.f && B[3].z < 0.f) ? (B[3].z - 2.f * A[3].z) : B[3].z;
                s += u * u;
                u = (A[3].w < 0.f && B[3].w < 0.f) ? (B[3].w - 2.f * A[3].w) : B[3].w;
                s += u * u;
                acc3 += s;
            }
        } else {
            // partial tail chunk (n4 % CHUNK_F4 != 0): bounds-checked
            for (int i = base + t; i < n4; i += 256) {
                float4 b0 = src[i];
                float4 a0 = tgt[i];
                float u, s;
                u = (a0.x < 0.f && b0.x < 0.f) ? (b0.x - 2.f * a0.x) : b0.x;
                s = u * u;
                u = (a0.y < 0.f && b0.y < 0.f) ? (b0.y - 2.f * a0.y) : b0.y;
                s += u * u;
                u = (a0.z < 0.f && b0.z < 0.f) ? (b0.z - 2.f * a0.z) : b0.z;
                s += u * u;
                u = (a0.w < 0.f && b0.w < 0.f) ? (b0.w - 2.f * a0.w) : b0.w;
                s += u * u;
                acc0 += s;
            }
        }

        __syncthreads();  // prefetched s_chunk visible
        chunk = s_chunk;
    }

    // doubles only from here on (off the memory-paced path)
    double acc = ((double)acc0 + (double)acc1) + ((double)acc2 + (double)acc3);

    // warp reduce (double)
    #pragma unroll
    for (int off = 16; off > 0; off >>= 1)
        acc += __shfl_down_sync(0xFFFFFFFFu, acc, off);

    __shared__ double warp_sums[8];  // 256 threads = 8 warps
    const int lane = t & 31;
    const int wid  = t >> 5;
    if (lane == 0) warp_sums[wid] = acc;
    __syncthreads();

    __shared__ bool is_last;
    if (t == 0) {
        double v = warp_sums[0];
        #pragma unroll
        for (int w = 1; w < 8; w++) v += warp_sums[w];
        atomicAdd(&g_fdloss_sum, v);
        __threadfence();
        unsigned int ticket = atomicInc(&g_fdloss_tick, gridDim.x - 1u);
        is_last = (ticket == gridDim.x - 1u);
    }
    __syncthreads();

    if (is_last && t == 0) {
        __threadfence();
        double s = g_fdloss_sum;
        out[0] = (float)(s * inv_n);
        g_fdloss_sum = 0.0;              // restore state for next replay
        atomicExch(&g_fdloss_work, 0u);  // restore work counter
    }
}

extern "C" void kernel_launch(void* const* d_in, const int* in_sizes, int n_in,
                              void* d_out, int out_size) {
    const float* src = (const float*)d_in[0];  // source -> b
    const float* tgt = (const float*)d_in[1];  // target -> a
    float* out = (float*)d_out;

    const long long n = (long long)in_sizes[0];
    const int n4 = (int)(n / 4);   // n = 51,380,224 -> n4 = 12,845,056

    const int nchunk_full  = n4 / CHUNK_F4;                 // 12544 exact
    const int rem          = n4 - nchunk_full * CHUNK_F4;   // 0 for this shape
    const int nchunk_total = nchunk_full + (rem ? 1 : 0);

    const int threads = 256;
    int blocks = 148 * 8;
    if (blocks > nchunk_total) blocks = nchunk_total;
    if (blocks < 1) blocks = 1;

    fdloss_kernel<<<blocks, threads>>>(
        (const float4*)src, (const float4*)tgt, n4,
        nchunk_total, nchunk_full, out, 1.0 / (double)n);
}

// round 10
// speedup vs baseline: 1.0296x; 1.0025x over previous
#include <cuda_runtime.h>
#include <cuda_bf16.h>

// Scalar reduction: mean over all elements of
//   term = (a<0 && b<0) ? (b - 2a)^2 : b^2
// where a = target (d_in[1]), b = source (d_in[0]).
// Derivation: fdback - a = (a<0&&b<0) ? (b-a)-a = b-2a : (a-b)-a = -b.
//
// Single-kernel, self-resetting (graph-replay-safe) reduction with dynamic
// chunk scheduling. Chunk = 2048 float4 per array (32 KB/array): each thread
// processes 8 float4 per array as TWO front-batched groups of 8 LDG.128
// (4 src + 4 tgt), keeping per-warp MLP at 8 while halving the per-chunk
// atomic + barrier overhead vs the 1024-float4 version.

__device__ double       g_fdloss_sum;    // zero-init at load; last block resets
__device__ unsigned int g_fdloss_tick;   // wrapping ticket; self-resets
__device__ unsigned int g_fdloss_work;   // chunk counter; last block resets

#define CHUNK_F4 2048   // float4 per chunk per array = 32 KB/array

// one front-batched group: 4 src + 4 tgt float4 at i0 + {0,256,512,768}
__device__ __forceinline__ void fd_group(
    const float4* __restrict__ src, const float4* __restrict__ tgt, int i0,
    float& acc0, float& acc1, float& acc2, float& acc3)
{
    float4 B[4], A[4];
    #pragma unroll
    for (int k = 0; k < 4; k++) {
        B[k] = src[i0 + k * 256];
        A[k] = tgt[i0 + k * 256];
    }
    {
        float u, s;
        u = (A[0].x < 0.f && B[0].x < 0.f) ? (B[0].x - 2.f * A[0].x) : B[0].x;
        s = u * u;
        u = (A[0].y < 0.f && B[0].y < 0.f) ? (B[0].y - 2.f * A[0].y) : B[0].y;
        s += u * u;
        u = (A[0].z < 0.f && B[0].z < 0.f) ? (B[0].z - 2.f * A[0].z) : B[0].z;
        s += u * u;
        u = (A[0].w < 0.f && B[0].w < 0.f) ? (B[0].w - 2.f * A[0].w) : B[0].w;
        s += u * u;
        acc0 += s;
    }
    {
        float u, s;
        u = (A[1].x < 0.f && B[1].x < 0.f) ? (B[1].x - 2.f * A[1].x) : B[1].x;
        s = u * u;
        u = (A[1].y < 0.f && B[1].y < 0.f) ? (B[1].y - 2.f * A[1].y) : B[1].y;
        s += u * u;
        u = (A[1].z < 0.f && B[1].z < 0.f) ? (B[1].z - 2.f * A[1].z) : B[1].z;
        s += u * u;
        u = (A[1].w < 0.f && B[1].w < 0.f) ? (B[1].w - 2.f * A[1].w) : B[1].w;
        s += u * u;
        acc1 += s;
    }
    {
        float u, s;
        u = (A[2].x < 0.f && B[2].x < 0.f) ? (B[2].x - 2.f * A[2].x) : B[2].x;
        s = u * u;
        u = (A[2].y < 0.f && B[2].y < 0.f) ? (B[2].y - 2.f * A[2].y) : B[2].y;
        s += u * u;
        u = (A[2].z < 0.f && B[2].z < 0.f) ? (B[2].z - 2.f * A[2].z) : B[2].z;
        s += u * u;
        u = (A[2].w < 0.f && B[2].w < 0.f) ? (B[2].w - 2.f * A[2].w) : B[2].w;
        s += u * u;
        acc2 += s;
    }
    {
        float u, s;
        u = (A[3].x < 0.f && B[3].x < 0.f) ? (B[3].x - 2.f * A[3].x) : B[3].x;
        s = u * u;
        u = (A[3].y < 0.f && B[3].y < 0.f) ? (B[3].y - 2.f * A[3].y) : B[3].y;
        s += u * u;
        u = (A[3].z < 0.f && B[3].z < 0.f) ? (B[3].z - 2.f * A[3].z) : B[3].z;
        s += u * u;
        u = (A[3].w < 0.f && B[3].w < 0.f) ? (B[3].w - 2.f * A[3].w) : B[3].w;
        s += u * u;
        acc3 += s;
    }
}

__global__ __launch_bounds__(256) void fdloss_kernel(
    const float4* __restrict__ src,   // b
    const float4* __restrict__ tgt,   // a
    int n4,
    int nchunk_total,
    int nchunk_full,
    float* __restrict__ out,
    double inv_n)
{
    const int t = threadIdx.x;

    float acc0 = 0.f, acc1 = 0.f, acc2 = 0.f, acc3 = 0.f;

    __shared__ int s_chunk;
    if (t == 0) s_chunk = (int)atomicAdd(&g_fdloss_work, 1u);
    __syncthreads();
    int chunk = s_chunk;

    while (chunk < nchunk_total) {
        __syncthreads();  // all threads captured s_chunk
        if (t == 0) s_chunk = (int)atomicAdd(&g_fdloss_work, 1u);  // prefetch

        const int base = chunk * CHUNK_F4;

        if (chunk < nchunk_full) {
            // two front-batched 8-load groups (each: MLP_p1 = 8)
            fd_group(src, tgt, base + t,        acc0, acc1, acc2, acc3);
            fd_group(src, tgt, base + t + 1024, acc0, acc1, acc2, acc3);
        } else {
            // partial tail chunk (n4 % CHUNK_F4 != 0): bounds-checked
            for (int i = base + t; i < n4; i += 256) {
                float4 b0 = src[i];
                float4 a0 = tgt[i];
                float u, s;
                u = (a0.x < 0.f && b0.x < 0.f) ? (b0.x - 2.f * a0.x) : b0.x;
                s = u * u;
                u = (a0.y < 0.f && b0.y < 0.f) ? (b0.y - 2.f * a0.y) : b0.y;
                s += u * u;
                u = (a0.z < 0.f && b0.z < 0.f) ? (b0.z - 2.f * a0.z) : b0.z;
                s += u * u;
                u = (a0.w < 0.f && b0.w < 0.f) ? (b0.w - 2.f * a0.w) : b0.w;
                s += u * u;
                acc0 += s;
            }
        }

        __syncthreads();  // prefetched s_chunk visible
        chunk = s_chunk;
    }

    // doubles only from here on (off the memory-paced path)
    double acc = ((double)acc0 + (double)acc1) + ((double)acc2 + (double)acc3);

    // warp reduce (double)
    #pragma unroll
    for (int off = 16; off > 0; off >>= 1)
        acc += __shfl_down_sync(0xFFFFFFFFu, acc, off);

    __shared__ double warp_sums[8];  // 256 threads = 8 warps
    const int lane = t & 31;
    const int wid  = t >> 5;
    if (lane == 0) warp_sums[wid] = acc;
    __syncthreads();

    __shared__ bool is_last;
    if (t == 0) {
        double v = warp_sums[0];
        #pragma unroll
        for (int w = 1; w < 8; w++) v += warp_sums[w];
        atomicAdd(&g_fdloss_sum, v);
        __threadfence();
        unsigned int ticket = atomicInc(&g_fdloss_tick, gridDim.x - 1u);
        is_last = (ticket == gridDim.x - 1u);
    }
    __syncthreads();

    if (is_last && t == 0) {
        __threadfence();
        double s = g_fdloss_sum;
        out[0] = (float)(s * inv_n);
        g_fdloss_sum = 0.0;              // restore state for next replay
        atomicExch(&g_fdloss_work, 0u);  // restore work counter
    }
}

extern "C" void kernel_launch(void* const* d_in, const int* in_sizes, int n_in,
                              void* d_out, int out_size) {
    const float* src = (const float*)d_in[0];  // source -> b
    const float* tgt = (const float*)d_in[1];  // target -> a
    float* out = (float*)d_out;

    const long long n = (long long)in_sizes[0];
    const int n4 = (int)(n / 4);   // n = 51,380,224 -> n4 = 12,845,056

    const int nchunk_full  = n4 / CHUNK_F4;                 // 6272 exact
    const int rem          = n4 - nchunk_full * CHUNK_F4;   // 0 for this shape
    const int nchunk_total = nchunk_full + (rem ? 1 : 0);

    const int threads = 256;
    int blocks = 148 * 8;
    if (blocks > nchunk_total) blocks = nchunk_total;
    if (blocks < 1) blocks = 1;

    fdloss_kernel<<<blocks, threads>>>(
        (const float4*)src, (const float4*)tgt, n4,
        nchunk_total, nchunk_full, out, 1.0 / (double)n);
}

// round 11
// speedup vs baseline: 1.0327x; 1.0030x over previous
#include <cuda_runtime.h>
#include <cuda_bf16.h>

// Scalar reduction: mean over all elements of
//   term = (a<0 && b<0) ? (b - 2a)^2 : b^2
// where a = target (d_in[1]), b = source (d_in[0]).
// Derivation: fdback - a = (a<0&&b<0) ? (b-a)-a = b-2a : (a-b)-a = -b.
//
// Single-kernel, self-resetting (graph-replay-safe) reduction with dynamic
// chunk scheduling. Chunk = 2048 float4 per array (32 KB/array): each thread
// processes 8 float4 per array as TWO front-batched groups of 8 LDG.128.
// Grid sized to EXACTLY one resident wave (148 SMs x 6 CTAs at 38 regs) so
// no straggler CTAs launch after the work queue drains.

__device__ double       g_fdloss_sum;    // zero-init at load; last block resets
__device__ unsigned int g_fdloss_tick;   // wrapping ticket; self-resets
__device__ unsigned int g_fdloss_work;   // chunk counter; last block resets

#define CHUNK_F4 2048   // float4 per chunk per array = 32 KB/array

// one front-batched group: 4 src + 4 tgt float4 at i0 + {0,256,512,768}
__device__ __forceinline__ void fd_group(
    const float4* __restrict__ src, const float4* __restrict__ tgt, int i0,
    float& acc0, float& acc1, float& acc2, float& acc3)
{
    float4 B[4], A[4];
    #pragma unroll
    for (int k = 0; k < 4; k++) {
        B[k] = src[i0 + k * 256];
        A[k] = tgt[i0 + k * 256];
    }
    {
        float u, s;
        u = (A[0].x < 0.f && B[0].x < 0.f) ? (B[0].x - 2.f * A[0].x) : B[0].x;
        s = u * u;
        u = (A[0].y < 0.f && B[0].y < 0.f) ? (B[0].y - 2.f * A[0].y) : B[0].y;
        s += u * u;
        u = (A[0].z < 0.f && B[0].z < 0.f) ? (B[0].z - 2.f * A[0].z) : B[0].z;
        s += u * u;
        u = (A[0].w < 0.f && B[0].w < 0.f) ? (B[0].w - 2.f * A[0].w) : B[0].w;
        s += u * u;
        acc0 += s;
    }
    {
        float u, s;
        u = (A[1].x < 0.f && B[1].x < 0.f) ? (B[1].x - 2.f * A[1].x) : B[1].x;
        s = u * u;
        u = (A[1].y < 0.f && B[1].y < 0.f) ? (B[1].y - 2.f * A[1].y) : B[1].y;
        s += u * u;
        u = (A[1].z < 0.f && B[1].z < 0.f) ? (B[1].z - 2.f * A[1].z) : B[1].z;
        s += u * u;
        u = (A[1].w < 0.f && B[1].w < 0.f) ? (B[1].w - 2.f * A[1].w) : B[1].w;
        s += u * u;
        acc1 += s;
    }
    {
        float u, s;
        u = (A[2].x < 0.f && B[2].x < 0.f) ? (B[2].x - 2.f * A[2].x) : B[2].x;
        s = u * u;
        u = (A[2].y < 0.f && B[2].y < 0.f) ? (B[2].y - 2.f * A[2].y) : B[2].y;
        s += u * u;
        u = (A[2].z < 0.f && B[2].z < 0.f) ? (B[2].z - 2.f * A[2].z) : B[2].z;
        s += u * u;
        u = (A[2].w < 0.f && B[2].w < 0.f) ? (B[2].w - 2.f * A[2].w) : B[2].w;
        s += u * u;
        acc2 += s;
    }
    {
        float u, s;
        u = (A[3].x < 0.f && B[3].x < 0.f) ? (B[3].x - 2.f * A[3].x) : B[3].x;
        s = u * u;
        u = (A[3].y < 0.f && B[3].y < 0.f) ? (B[3].y - 2.f * A[3].y) : B[3].y;
        s += u * u;
        u = (A[3].z < 0.f && B[3].z < 0.f) ? (B[3].z - 2.f * A[3].z) : B[3].z;
        s += u * u;
        u = (A[3].w < 0.f && B[3].w < 0.f) ? (B[3].w - 2.f * A[3].w) : B[3].w;
        s += u * u;
        acc3 += s;
    }
}

__global__ __launch_bounds__(256) void fdloss_kernel(
    const float4* __restrict__ src,   // b
    const float4* __restrict__ tgt,   // a
    int n4,
    int nchunk_total,
    int nchunk_full,
    float* __restrict__ out,
    double inv_n)
{
    const int t = threadIdx.x;

    float acc0 = 0.f, acc1 = 0.f, acc2 = 0.f, acc3 = 0.f;

    __shared__ int s_chunk;
    if (t == 0) s_chunk = (int)atomicAdd(&g_fdloss_work, 1u);
    __syncthreads();
    int chunk = s_chunk;

    while (chunk < nchunk_total) {
        __syncthreads();  // all threads captured s_chunk
        if (t == 0) s_chunk = (int)atomicAdd(&g_fdloss_work, 1u);  // prefetch

        const int base = chunk * CHUNK_F4;

        if (chunk < nchunk_full) {
            // two front-batched 8-load groups (each: MLP_p1 = 8)
            fd_group(src, tgt, base + t,        acc0, acc1, acc2, acc3);
            fd_group(src, tgt, base + t + 1024, acc0, acc1, acc2, acc3);
        } else {
            // partial tail chunk (n4 % CHUNK_F4 != 0): bounds-checked
            for (int i = base + t; i < n4; i += 256) {
                float4 b0 = src[i];
                float4 a0 = tgt[i];
                float u, s;
                u = (a0.x < 0.f && b0.x < 0.f) ? (b0.x - 2.f * a0.x) : b0.x;
                s = u * u;
                u = (a0.y < 0.f && b0.y < 0.f) ? (b0.y - 2.f * a0.y) : b0.y;
                s += u * u;
                u = (a0.z < 0.f && b0.z < 0.f) ? (b0.z - 2.f * a0.z) : b0.z;
                s += u * u;
                u = (a0.w < 0.f && b0.w < 0.f) ? (b0.w - 2.f * a0.w) : b0.w;
                s += u * u;
                acc0 += s;
            }
        }

        __syncthreads();  // prefetched s_chunk visible
        chunk = s_chunk;
    }

    // doubles only from here on (off the memory-paced path)
    double acc = ((double)acc0 + (double)acc1) + ((double)acc2 + (double)acc3);

    // warp reduce (double)
    #pragma unroll
    for (int off = 16; off > 0; off >>= 1)
        acc += __shfl_down_sync(0xFFFFFFFFu, acc, off);

    __shared__ double warp_sums[8];  // 256 threads = 8 warps
    const int lane = t & 31;
    const int wid  = t >> 5;
    if (lane == 0) warp_sums[wid] = acc;
    __syncthreads();

    __shared__ bool is_last;
    if (t == 0) {
        double v = warp_sums[0];
        #pragma unroll
        for (int w = 1; w < 8; w++) v += warp_sums[w];
        atomicAdd(&g_fdloss_sum, v);
        __threadfence();
        unsigned int ticket = atomicInc(&g_fdloss_tick, gridDim.x - 1u);
        is_last = (ticket == gridDim.x - 1u);
    }
    __syncthreads();

    if (is_last && t == 0) {
        __threadfence();
        double s = g_fdloss_sum;
        out[0] = (float)(s * inv_n);
        g_fdloss_sum = 0.0;              // restore state for next replay
        atomicExch(&g_fdloss_work, 0u);  // restore work counter
    }
}

extern "C" void kernel_launch(void* const* d_in, const int* in_sizes, int n_in,
                              void* d_out, int out_size) {
    const float* src = (const float*)d_in[0];  // source -> b
    const float* tgt = (const float*)d_in[1];  // target -> a
    float* out = (float*)d_out;

    const long long n = (long long)in_sizes[0];
    const int n4 = (int)(n / 4);   // n = 51,380,224 -> n4 = 12,845,056

    const int nchunk_full  = n4 / CHUNK_F4;                 // 6272 exact
    const int rem          = n4 - nchunk_full * CHUNK_F4;   // 0 for this shape
    const int nchunk_total = nchunk_full + (rem ? 1 : 0);

    const int threads = 256;
    // One resident wave: 148 SMs x 6 CTAs/SM (38 regs, 256 thr -> occ 6).
    int blocks = 148 * 6;
    if (blocks > nchunk_total) blocks = nchunk_total;
    if (blocks < 1) blocks = 1;

    fdloss_kernel<<<blocks, threads>>>(
        (const float4*)src, (const float4*)tgt, n4,
        nchunk_total, nchunk_full, out, 1.0 / (double)n);
}